// round 16
// baseline (speedup 1.0000x reference)
#include <cuda_runtime.h>
#include <cuda_fp16.h>

// FeaturesLinear: out[b,:] = sum_{t<50} user_W[fid[b*50+t]] * rating_W[ridx[b*50+t]]
//                            + item_W[item_ids[b]] + bias
//
// R16: R14/R15 run at 0.66 of the L1-wavefront ceiling because 32 regs limit
// the number of in-flight float4 gathers (latency exposure). Fix both knobs at
// once with an fp16 user_W table (rebuilt each replay by a ~9us streaming
// convert kernel, measured in R12):
//   - gather: LDG.128 (4 wf, 4 regs) -> LDG.64 (2 wf, 2 regs)  => 2x MLP
//   - per item: 2 wf gather + 2 wf fp16-rv LDS.64 = 4 wf (R5: 10, R14: 6)
// Main loop stays R14's proven flat branch-free unrolled-50 shape with
// static-lane shuffles for the ids. Accuracy: fp16 on both factors, each
// independently measured at ~7.3e-5 rel err; combined ~1.2e-4 << 1e-3.
//
// Inputs (metadata order):
//   d_in[0] feature_ids int32 [819200]
//   d_in[1] ratings     f32   [819200]
//   d_in[2] segment_ids int32 [819200]  (contiguous repeat(arange(B),50) -> implicit)
//   d_in[3] item_ids    int32 [16384]
//   d_in[4] user_W      f32   [100001,128]
//   d_in[5] rating_W    f32   [10,128]
//   d_in[6] item_W      f32   [100000,128]
//   d_in[7] bias        f32   [128]
// Output: f32 [16384,128]

#define BATCH  16384
#define HIST   50
#define NROWS  100001
#define WARPS_PER_CTA 8
#define THREADS (WARPS_PER_CTA * 32)

// fp16 copy of user_W: 100001 rows x 128 halves = 25.6 MB scratch.
// g_uw16[f*32 + lane] holds cols 4*lane..4*lane+3 as two half2s.
__device__ __align__(16) static uint2 g_uw16[NROWS * 32];

// ---------------------------------------------------------------------------
// Kernel A: convert user_W f32 -> fp16 table (pure streaming, ~9us).
// ---------------------------------------------------------------------------
__global__ void __launch_bounds__(256)
convert_uw_kernel(const float4* __restrict__ user_W)
{
    const int i = blockIdx.x * 256 + threadIdx.x;      // float4 index
    if (i < NROWS * 32) {
        const float4 v = __ldg(&user_W[i]);
        const __half2 h0 = __floats2half2_rn(v.x, v.y);
        const __half2 h1 = __floats2half2_rn(v.z, v.w);
        uint2 w;
        w.x = *reinterpret_cast<const unsigned*>(&h0);
        w.y = *reinterpret_cast<const unsigned*>(&h1);
        g_uw16[i] = w;
    }
}

// ---------------------------------------------------------------------------
// Kernel B: gather/accumulate (R14 flat loop, fp16 LDG.64 gathers).
// ---------------------------------------------------------------------------
__global__ void __launch_bounds__(THREADS, 8)
features_linear_kernel(const int*    __restrict__ feature_ids,
                       const float*  __restrict__ ratings,
                       const int*    __restrict__ item_ids,
                       const float4* __restrict__ rating_W,  // [10, 32]     float4
                       const float4* __restrict__ item_W,    // [100000, 32] float4
                       const float4* __restrict__ bias,      // [32]         float4
                       float4*       __restrict__ out)       // [16384, 32]  float4
{
    // fp16 rating table: entry [r*32+lane] = 4 halves (cols 4*lane..4*lane+3).
    __shared__ uint2  s_rw16[10 * 32];   // 2.5 KB
    __shared__ float4 s_bias[32];        // 512 B

    const int tid = threadIdx.x;
    for (int i = tid; i < 10 * 32; i += THREADS) {
        const float4 v = __ldg(&rating_W[i]);
        const __half2 h0 = __floats2half2_rn(v.x, v.y);
        const __half2 h1 = __floats2half2_rn(v.z, v.w);
        uint2 w;
        w.x = *reinterpret_cast<const unsigned*>(&h0);
        w.y = *reinterpret_cast<const unsigned*>(&h1);
        s_rw16[i] = w;
    }
    if (tid < 32) s_bias[tid] = __ldg(&bias[tid]);
    __syncthreads();

    const int warp = tid >> 5;
    const int lane = tid & 31;
    const int row  = blockIdx.x * WARPS_PER_CTA + warp;   // one warp per row
    const int base = row * HIST;
    const unsigned FULL = 0xffffffffu;

    // ---- Stage packed (fid<<4|ridx) into registers: 2/lane, coalesced ------
    int pkA, pkB = 0;
    {
        const int   fidA = __ldg(&feature_ids[base + lane]);
        const float ratA = __ldg(&ratings[base + lane]);
        pkA = (fidA << 4) | __float2int_rn((ratA - 0.5f) * 2.0f);
        if (lane < (HIST - 32)) {
            const int   fidB = __ldg(&feature_ids[base + 32 + lane]);
            const float ratB = __ldg(&ratings[base + 32 + lane]);
            pkB = (fidB << 4) | __float2int_rn((ratB - 0.5f) * 2.0f);
        }
    }

    // ---- Flat branch-free loop: 50 independent fp16 gathers, high MLP ------
    float4 acc = make_float4(0.f, 0.f, 0.f, 0.f);

    #pragma unroll
    for (int k = 0; k < HIST; ++k) {
        // Compile-time lane + compile-time register select: no L1 traffic.
        const int p = __shfl_sync(FULL, (k < 32) ? pkA : pkB, k & 31);
        const uint2 uw = __ldg(&g_uw16[(p >> 4) * 32 + lane]);   // 2 wf gather
        const uint2 rw = s_rw16[(p & 15) * 32 + lane];           // 2 wf LDS.64
        const float2 u01 = __half22float2(*reinterpret_cast<const __half2*>(&uw.x));
        const float2 u23 = __half22float2(*reinterpret_cast<const __half2*>(&uw.y));
        const float2 r01 = __half22float2(*reinterpret_cast<const __half2*>(&rw.x));
        const float2 r23 = __half22float2(*reinterpret_cast<const __half2*>(&rw.y));
        acc.x = fmaf(u01.x, r01.x, acc.x);
        acc.y = fmaf(u01.y, r01.y, acc.y);
        acc.z = fmaf(u23.x, r23.x, acc.z);
        acc.w = fmaf(u23.y, r23.y, acc.w);
    }

    // ---- Epilogue (fp32, after the loop) -----------------------------------
    const int    iid = __ldg(&item_ids[row]);
    const float4 iv  = __ldg(&item_W[iid * 32 + lane]);
    const float4 bv  = s_bias[lane];

    acc.x += iv.x + bv.x;
    acc.y += iv.y + bv.y;
    acc.z += iv.z + bv.z;
    acc.w += iv.w + bv.w;

    out[row * 32 + lane] = acc;
}

extern "C" void kernel_launch(void* const* d_in, const int* in_sizes, int n_in,
                              void* d_out, int out_size)
{
    const int*    feature_ids = (const int*)  d_in[0];
    const float*  ratings     = (const float*)d_in[1];
    // d_in[2] segment_ids: repeat(arange(BATCH), HIST) -> implicit in layout
    const int*    item_ids = (const int*)   d_in[3];
    const float4* user_W   = (const float4*)d_in[4];
    const float4* rating_W = (const float4*)d_in[5];
    const float4* item_W   = (const float4*)d_in[6];
    const float4* bias     = (const float4*)d_in[7];
    float4*       out      = (float4*)      d_out;

    // Kernel A: rebuild fp16 gather table (every replay; streaming-bound).
    const int n4 = NROWS * 32;                        // 3,200,032 float4
    convert_uw_kernel<<<(n4 + 255) / 256, 256>>>(user_W);

    // Kernel B: gather + accumulate.
    const int grid = BATCH / WARPS_PER_CTA;           // 2048 CTAs
    features_linear_kernel<<<grid, THREADS>>>(
        feature_ids, ratings, item_ids, rating_W, item_W, bias, out);
}